// round 1
// baseline (speedup 1.0000x reference)
#include <cuda_runtime.h>
#include <math.h>

#define T_SEQ 2048
#define B_SZ  2
#define C_DIM 1024
#define H_NUM 16
#define D_HEAD 64
#define M_ROWS (T_SEQ * B_SZ)   // 4096

// Scratch (allocation-free rule: __device__ globals)
__device__ float g_q[(size_t)B_SZ * H_NUM * T_SEQ * D_HEAD];   // 16 MB
__device__ float g_k[(size_t)B_SZ * H_NUM * T_SEQ * D_HEAD];   // 16 MB
__device__ float g_v[(size_t)B_SZ * H_NUM * T_SEQ * D_HEAD];   // 16 MB
__device__ float g_ctx[(size_t)M_ROWS * C_DIM];                // 16 MB

// ---------------------------------------------------------------------------
// NT GEMM: C[M,N] = A[M,K] * W[N,K]^T   (both K-contiguous row-major)
// M=4096, N=1024, K=1024. Tile 64x64, BK=16, 256 threads, 4x4 per thread.
// mode 0/1/2: A = A_in (x), write to g_q/g_k/g_v with (B,H,T,D) remap
// mode 3:     A = g_ctx, plain row-major write to out_plain
// ---------------------------------------------------------------------------
__global__ __launch_bounds__(256) void gemm_nt_kernel(
    const float* __restrict__ A_in, const float* __restrict__ W,
    float* __restrict__ out_plain, int mode)
{
    __shared__ float As[16][68];   // [k][m], padded
    __shared__ float Bs[16][68];   // [k][n], padded

    const float* A = (mode == 3) ? g_ctx : A_in;

    const int tid = threadIdx.x;
    const int tx = tid & 15;        // 0..15 -> n
    const int ty = tid >> 4;        // 0..15 -> m
    const int bm = blockIdx.y * 64;
    const int bn = blockIdx.x * 64;

    // cooperative load mapping: each thread loads one float4 of A and W per BK step
    const int lr = tid >> 2;          // 0..63 tile row
    const int lc = (tid & 3) * 4;     // k offset within BK

    float acc[4][4];
    #pragma unroll
    for (int i = 0; i < 4; i++)
        #pragma unroll
        for (int j = 0; j < 4; j++) acc[i][j] = 0.f;

    for (int k0 = 0; k0 < C_DIM; k0 += 16) {
        float4 av = *(const float4*)(A + (size_t)(bm + lr) * C_DIM + k0 + lc);
        float4 bv = *(const float4*)(W + (size_t)(bn + lr) * C_DIM + k0 + lc);
        As[lc + 0][lr] = av.x; As[lc + 1][lr] = av.y;
        As[lc + 2][lr] = av.z; As[lc + 3][lr] = av.w;
        Bs[lc + 0][lr] = bv.x; Bs[lc + 1][lr] = bv.y;
        Bs[lc + 2][lr] = bv.z; Bs[lc + 3][lr] = bv.w;
        __syncthreads();

        #pragma unroll
        for (int kk = 0; kk < 16; kk++) {
            float4 a4 = *(const float4*)&As[kk][ty * 4];
            float4 b4 = *(const float4*)&Bs[kk][tx * 4];
            float ar[4] = {a4.x, a4.y, a4.z, a4.w};
            float br[4] = {b4.x, b4.y, b4.z, b4.w};
            #pragma unroll
            for (int i = 0; i < 4; i++)
                #pragma unroll
                for (int j = 0; j < 4; j++)
                    acc[i][j] = fmaf(ar[i], br[j], acc[i][j]);
        }
        __syncthreads();
    }

    if (mode == 3) {
        #pragma unroll
        for (int i = 0; i < 4; i++) {
            int m = bm + ty * 4 + i;
            float4 o = make_float4(acc[i][0], acc[i][1], acc[i][2], acc[i][3]);
            *(float4*)(out_plain + (size_t)m * C_DIM + bn + tx * 4) = o;
        }
    } else {
        float* dst = (mode == 0) ? g_q : (mode == 1) ? g_k : g_v;
        #pragma unroll
        for (int i = 0; i < 4; i++) {
            int m = bm + ty * 4 + i;
            int t = m / B_SZ;
            int b = m % B_SZ;
            #pragma unroll
            for (int j = 0; j < 4; j++) {
                int n = bn + tx * 4 + j;
                int h = n >> 6;          // n / 64
                int d = n & 63;          // n % 64
                dst[(((size_t)b * H_NUM + h) * T_SEQ + t) * D_HEAD + d] = acc[i][j];
            }
        }
    }
}

// ---------------------------------------------------------------------------
// Causal flash attention, fp32. One thread owns one q row (128 rows / block).
// K/V staged in smem in 32-row tiles; online softmax in registers.
// grid = (T/128, H, B), block = 128
// ---------------------------------------------------------------------------
__global__ __launch_bounds__(128) void attn_kernel()
{
    const int qb = blockIdx.x;
    const int h  = blockIdx.y;
    const int b  = blockIdx.z;
    const size_t base = (((size_t)b * H_NUM + h) * T_SEQ) * D_HEAD;
    const float* Qp = g_q + base;
    const float* Kp = g_k + base;
    const float* Vp = g_v + base;

    const int tid = threadIdx.x;
    const int qi = qb * 128 + tid;

    __shared__ float Ks[32][64];
    __shared__ float Vs[32][64];

    float qreg[64];
    #pragma unroll
    for (int d4 = 0; d4 < 16; d4++) {
        float4 v = *(const float4*)(Qp + (size_t)qi * 64 + d4 * 4);
        qreg[d4 * 4 + 0] = v.x; qreg[d4 * 4 + 1] = v.y;
        qreg[d4 * 4 + 2] = v.z; qreg[d4 * 4 + 3] = v.w;
    }

    float mrow = -1e30f, lrow = 0.f;
    float acc[64];
    #pragma unroll
    for (int d = 0; d < 64; d++) acc[d] = 0.f;

    const int nkb = qb * 4 + 4;   // causal: k tiles up to the diagonal of this q block
    for (int kb = 0; kb < nkb; kb++) {
        // cooperative load: 32x64 K and V tiles, float4, coalesced
        #pragma unroll
        for (int it = 0; it < 4; it++) {
            int idx = tid + it * 128;         // 0..511 float4 slots
            int r = idx >> 4;
            int c = (idx & 15) * 4;
            *(float4*)&Ks[r][c] = *(const float4*)(Kp + (size_t)(kb * 32 + r) * 64 + c);
            *(float4*)&Vs[r][c] = *(const float4*)(Vp + (size_t)(kb * 32 + r) * 64 + c);
        }
        __syncthreads();

        float s[32];
        #pragma unroll
        for (int j = 0; j < 32; j++) {
            float dot = 0.f;
            #pragma unroll
            for (int d = 0; d < 64; d++) dot = fmaf(qreg[d], Ks[j][d], dot);
            s[j] = (kb * 32 + j <= qi) ? dot * 0.125f : -1e30f;
        }

        float mb = mrow;
        #pragma unroll
        for (int j = 0; j < 32; j++) mb = fmaxf(mb, s[j]);

        float corr = __expf(mrow - mb);
        mrow = mb;
        lrow *= corr;
        #pragma unroll
        for (int d = 0; d < 64; d++) acc[d] *= corr;

        #pragma unroll
        for (int j = 0; j < 32; j++) {
            float p = __expf(s[j] - mb);
            lrow += p;
            #pragma unroll
            for (int d = 0; d < 64; d++)
                acc[d] = fmaf(p, Vs[j][d], acc[d]);
        }
        __syncthreads();
    }

    float inv = 1.0f / lrow;
    float* dst = g_ctx + ((size_t)qi * B_SZ + b) * C_DIM + h * D_HEAD;
    #pragma unroll
    for (int d4 = 0; d4 < 16; d4++) {
        float4 o = make_float4(acc[d4 * 4 + 0] * inv, acc[d4 * 4 + 1] * inv,
                               acc[d4 * 4 + 2] * inv, acc[d4 * 4 + 3] * inv);
        *(float4*)(dst + d4 * 4) = o;
    }
}

// ---------------------------------------------------------------------------
extern "C" void kernel_launch(void* const* d_in, const int* in_sizes, int n_in,
                              void* d_out, int out_size)
{
    const float* x  = (const float*)d_in[0];
    const float* Wq = (const float*)d_in[1];
    const float* Wk = (const float*)d_in[2];
    const float* Wv = (const float*)d_in[3];
    const float* Wo = (const float*)d_in[4];
    float* out = (float*)d_out;

    dim3 gg(C_DIM / 64, M_ROWS / 64);   // (16, 64) = 1024 blocks
    gemm_nt_kernel<<<gg, 256>>>(x, Wq, nullptr, 0);
    gemm_nt_kernel<<<gg, 256>>>(x, Wk, nullptr, 1);
    gemm_nt_kernel<<<gg, 256>>>(x, Wv, nullptr, 2);

    dim3 ga(T_SEQ / 128, H_NUM, B_SZ);  // (16, 16, 2) = 512 blocks
    attn_kernel<<<ga, 128>>>();

    gemm_nt_kernel<<<gg, 256>>>(nullptr, Wo, out, 3);
}

// round 2
// speedup vs baseline: 1.4236x; 1.4236x over previous
#include <cuda_runtime.h>
#include <math.h>
#include <stdint.h>

#define T_SEQ 2048
#define B_SZ  2
#define C_DIM 1024
#define H_NUM 16
#define D_HEAD 64
#define M_ROWS (T_SEQ * B_SZ)   // 4096

// Scratch (allocation-free rule: __device__ globals)
__device__ float g_q[(size_t)B_SZ * H_NUM * T_SEQ * D_HEAD];   // 16 MB
__device__ float g_k[(size_t)B_SZ * H_NUM * T_SEQ * D_HEAD];   // 16 MB
__device__ float g_v[(size_t)B_SZ * H_NUM * T_SEQ * D_HEAD];   // 16 MB
__device__ float g_ctx[(size_t)M_ROWS * C_DIM];                // 16 MB

__device__ __forceinline__ float cvt_tf32(float x) {
    uint32_t r;
    asm("cvt.rna.tf32.f32 %0, %1;" : "=r"(r) : "f"(x));
    return __uint_as_float(r);
}

// ---------------------------------------------------------------------------
// TF32 tensor-core NT GEMM: C[M,N] = A[M,K] * W[N,K]^T
// M=4096, N=1024, K=1024. CTA tile 128x64, BK=32, 256 threads (8 warps, 4x2).
// Warp tile 32x32 = 2(m) x 4(n) m16n8k8 fragments.
// mode 0/1/2: A = x, write g_q/g_k/g_v with (B,H,T,D) remap
// mode 3:     A = g_ctx, row-major write to out_plain
// ---------------------------------------------------------------------------
#define BM 128
#define BN 64
#define BK 32
#define SPAD 36   // 36 mod 32 = 4 -> conflict-free fragment loads

__global__ __launch_bounds__(256) void gemm_tf32_kernel(
    const float* __restrict__ A_in, const float* __restrict__ W,
    float* __restrict__ out_plain, int mode)
{
    __shared__ float As[BM][SPAD];   // 18 KB
    __shared__ float Bs[BN][SPAD];   //  9 KB

    const float* A = (mode == 3) ? g_ctx : A_in;

    const int tid  = threadIdx.x;
    const int lane = tid & 31;
    const int wid  = tid >> 5;
    const int gid  = lane >> 2;     // 0..7
    const int tig  = lane & 3;      // 0..3
    const int wm   = wid >> 1;      // 0..3
    const int wn   = wid & 1;       // 0..1
    const int bm   = blockIdx.y * BM;
    const int bn   = blockIdx.x * BN;

    // global load mapping: each thread loads float4s; 32 rows per pass
    const int lr = tid >> 3;          // 0..31
    const int lc = (tid & 7) * 4;     // 0..28

    float c[2][4][4];
    #pragma unroll
    for (int mt = 0; mt < 2; mt++)
        #pragma unroll
        for (int nt = 0; nt < 4; nt++)
            #pragma unroll
            for (int i = 0; i < 4; i++) c[mt][nt][i] = 0.f;

    for (int k0 = 0; k0 < C_DIM; k0 += BK) {
        #pragma unroll
        for (int i = 0; i < 4; i++) {
            float4 v = *(const float4*)(A + (size_t)(bm + lr + i * 32) * C_DIM + k0 + lc);
            As[lr + i * 32][lc + 0] = cvt_tf32(v.x);
            As[lr + i * 32][lc + 1] = cvt_tf32(v.y);
            As[lr + i * 32][lc + 2] = cvt_tf32(v.z);
            As[lr + i * 32][lc + 3] = cvt_tf32(v.w);
        }
        #pragma unroll
        for (int i = 0; i < 2; i++) {
            float4 v = *(const float4*)(W + (size_t)(bn + lr + i * 32) * C_DIM + k0 + lc);
            Bs[lr + i * 32][lc + 0] = cvt_tf32(v.x);
            Bs[lr + i * 32][lc + 1] = cvt_tf32(v.y);
            Bs[lr + i * 32][lc + 2] = cvt_tf32(v.z);
            Bs[lr + i * 32][lc + 3] = cvt_tf32(v.w);
        }
        __syncthreads();

        #pragma unroll
        for (int kk = 0; kk < 4; kk++) {
            const int k8 = kk * 8;
            uint32_t a[2][4], b[4][2];
            #pragma unroll
            for (int mt = 0; mt < 2; mt++) {
                int r = wm * 32 + mt * 16 + gid;
                a[mt][0] = __float_as_uint(As[r    ][k8 + tig]);
                a[mt][1] = __float_as_uint(As[r + 8][k8 + tig]);
                a[mt][2] = __float_as_uint(As[r    ][k8 + tig + 4]);
                a[mt][3] = __float_as_uint(As[r + 8][k8 + tig + 4]);
            }
            #pragma unroll
            for (int nt = 0; nt < 4; nt++) {
                int cn = wn * 32 + nt * 8 + gid;
                b[nt][0] = __float_as_uint(Bs[cn][k8 + tig]);
                b[nt][1] = __float_as_uint(Bs[cn][k8 + tig + 4]);
            }
            #pragma unroll
            for (int mt = 0; mt < 2; mt++)
                #pragma unroll
                for (int nt = 0; nt < 4; nt++) {
                    asm volatile(
                        "mma.sync.aligned.m16n8k8.row.col.f32.tf32.tf32.f32 "
                        "{%0,%1,%2,%3}, {%4,%5,%6,%7}, {%8,%9}, {%0,%1,%2,%3};"
                        : "+f"(c[mt][nt][0]), "+f"(c[mt][nt][1]),
                          "+f"(c[mt][nt][2]), "+f"(c[mt][nt][3])
                        : "r"(a[mt][0]), "r"(a[mt][1]), "r"(a[mt][2]), "r"(a[mt][3]),
                          "r"(b[nt][0]), "r"(b[nt][1]));
                }
        }
        __syncthreads();
    }

    // epilogue
    if (mode == 3) {
        #pragma unroll
        for (int mt = 0; mt < 2; mt++)
            #pragma unroll
            for (int nt = 0; nt < 4; nt++) {
                int row0 = bm + wm * 32 + mt * 16 + gid;
                int col0 = bn + wn * 32 + nt * 8 + tig * 2;
                *(float2*)(out_plain + (size_t)row0 * C_DIM + col0) =
                    make_float2(c[mt][nt][0], c[mt][nt][1]);
                *(float2*)(out_plain + (size_t)(row0 + 8) * C_DIM + col0) =
                    make_float2(c[mt][nt][2], c[mt][nt][3]);
            }
    } else {
        float* dst = (mode == 0) ? g_q : (mode == 1) ? g_k : g_v;
        #pragma unroll
        for (int mt = 0; mt < 2; mt++)
            #pragma unroll
            for (int nt = 0; nt < 4; nt++) {
                int row0 = bm + wm * 32 + mt * 16 + gid;
                int col0 = bn + wn * 32 + nt * 8 + tig * 2;
                #pragma unroll
                for (int i = 0; i < 4; i++) {
                    int m = row0 + (i >> 1) * 8;
                    int n = col0 + (i & 1);
                    int t = m / B_SZ, bb = m % B_SZ;
                    int h = n >> 6, d = n & 63;
                    dst[(((size_t)bb * H_NUM + h) * T_SEQ + t) * D_HEAD + d] = c[mt][nt][i];
                }
            }
    }
}

// ---------------------------------------------------------------------------
// Causal flash attention, fp32, float4-vectorized smem access.
// One thread per q row (128 rows / block). grid = (T/128, H, B), block = 128
// Heavy (high-qb) blocks scheduled first via reversed blockIdx.x.
// ---------------------------------------------------------------------------
__global__ __launch_bounds__(128) void attn_kernel()
{
    const int qb = (gridDim.x - 1) - blockIdx.x;
    const int h  = blockIdx.y;
    const int b  = blockIdx.z;
    const size_t base = (((size_t)b * H_NUM + h) * T_SEQ) * D_HEAD;
    const float* Qp = g_q + base;
    const float* Kp = g_k + base;
    const float* Vp = g_v + base;

    const int tid = threadIdx.x;
    const int qi = qb * 128 + tid;

    __shared__ float Ks[32][64];
    __shared__ float Vs[32][64];

    float4 qreg[16];
    #pragma unroll
    for (int d4 = 0; d4 < 16; d4++)
        qreg[d4] = *(const float4*)(Qp + (size_t)qi * 64 + d4 * 4);

    float mrow = -1e30f, lrow = 0.f;
    float4 acc[16];
    #pragma unroll
    for (int d4 = 0; d4 < 16; d4++) acc[d4] = make_float4(0.f, 0.f, 0.f, 0.f);

    const int nkb = qb * 4 + 4;
    for (int kb = 0; kb < nkb; kb++) {
        #pragma unroll
        for (int it = 0; it < 4; it++) {
            int idx = tid + it * 128;
            int r = idx >> 4;
            int cc = (idx & 15) * 4;
            *(float4*)&Ks[r][cc] = *(const float4*)(Kp + (size_t)(kb * 32 + r) * 64 + cc);
            *(float4*)&Vs[r][cc] = *(const float4*)(Vp + (size_t)(kb * 32 + r) * 64 + cc);
        }
        __syncthreads();

        float s[32];
        #pragma unroll
        for (int j = 0; j < 32; j++) {
            float dot = 0.f;
            #pragma unroll
            for (int d4 = 0; d4 < 16; d4++) {
                float4 kv = *(const float4*)&Ks[j][d4 * 4];
                dot = fmaf(qreg[d4].x, kv.x, dot);
                dot = fmaf(qreg[d4].y, kv.y, dot);
                dot = fmaf(qreg[d4].z, kv.z, dot);
                dot = fmaf(qreg[d4].w, kv.w, dot);
            }
            s[j] = (kb * 32 + j <= qi) ? dot * 0.125f : -1e30f;
        }

        float mb = mrow;
        #pragma unroll
        for (int j = 0; j < 32; j++) mb = fmaxf(mb, s[j]);

        float corr = __expf(mrow - mb);
        mrow = mb;
        lrow *= corr;
        #pragma unroll
        for (int d4 = 0; d4 < 16; d4++) {
            acc[d4].x *= corr; acc[d4].y *= corr;
            acc[d4].z *= corr; acc[d4].w *= corr;
        }

        #pragma unroll
        for (int j = 0; j < 32; j++) {
            float p = __expf(s[j] - mb);
            lrow += p;
            #pragma unroll
            for (int d4 = 0; d4 < 16; d4++) {
                float4 vv = *(const float4*)&Vs[j][d4 * 4];
                acc[d4].x = fmaf(p, vv.x, acc[d4].x);
                acc[d4].y = fmaf(p, vv.y, acc[d4].y);
                acc[d4].z = fmaf(p, vv.z, acc[d4].z);
                acc[d4].w = fmaf(p, vv.w, acc[d4].w);
            }
        }
        __syncthreads();
    }

    float inv = 1.0f / lrow;
    float* dst = g_ctx + ((size_t)qi * B_SZ + b) * C_DIM + h * D_HEAD;
    #pragma unroll
    for (int d4 = 0; d4 < 16; d4++) {
        float4 o = make_float4(acc[d4].x * inv, acc[d4].y * inv,
                               acc[d4].z * inv, acc[d4].w * inv);
        *(float4*)(dst + d4 * 4) = o;
    }
}

// ---------------------------------------------------------------------------
extern "C" void kernel_launch(void* const* d_in, const int* in_sizes, int n_in,
                              void* d_out, int out_size)
{
    const float* x  = (const float*)d_in[0];
    const float* Wq = (const float*)d_in[1];
    const float* Wk = (const float*)d_in[2];
    const float* Wv = (const float*)d_in[3];
    const float* Wo = (const float*)d_in[4];
    float* out = (float*)d_out;

    dim3 gg(C_DIM / BN, M_ROWS / BM);   // (16, 32) = 512 blocks
    gemm_tf32_kernel<<<gg, 256>>>(x, Wq, nullptr, 0);
    gemm_tf32_kernel<<<gg, 256>>>(x, Wk, nullptr, 1);
    gemm_tf32_kernel<<<gg, 256>>>(x, Wv, nullptr, 2);

    dim3 ga(T_SEQ / 128, H_NUM, B_SZ);  // (16, 16, 2) = 512 blocks
    attn_kernel<<<ga, 128>>>();

    gemm_tf32_kernel<<<gg, 256>>>(nullptr, Wo, out, 3);
}

// round 3
// speedup vs baseline: 3.4033x; 2.3906x over previous
#include <cuda_runtime.h>
#include <math.h>
#include <stdint.h>

#define T_SEQ 2048
#define B_SZ  2
#define C_DIM 1024
#define H_NUM 16
#define D_HEAD 64
#define M_ROWS (T_SEQ * B_SZ)   // 4096

__device__ float g_q[(size_t)B_SZ * H_NUM * T_SEQ * D_HEAD];
__device__ float g_k[(size_t)B_SZ * H_NUM * T_SEQ * D_HEAD];
__device__ float g_v[(size_t)B_SZ * H_NUM * T_SEQ * D_HEAD];
__device__ float g_ctx[(size_t)M_ROWS * C_DIM];

__device__ __forceinline__ float cvt_tf32(float x) {
    uint32_t r;
    asm("cvt.rna.tf32.f32 %0, %1;" : "=r"(r) : "f"(x));
    return __uint_as_float(r);
}

// Fast exp on the FFMA pipe (avoids MUFU bottleneck). |rel err| ~2e-6.
__device__ __forceinline__ float fast_exp(float x) {
    x = fmaxf(x, -80.f);
    float y = x * 1.44269504f;          // log2(e)
    float t = y + 12582912.f;           // 1.5 * 2^23 round-to-int trick
    int   n = __float_as_int(t) - 0x4B400000;
    float f = y - (t - 12582912.f);     // f in [-0.5, 0.5]
    float p = 0.00133335581f;
    p = fmaf(p, f, 0.00961812911f);
    p = fmaf(p, f, 0.0555041087f);
    p = fmaf(p, f, 0.240226507f);
    p = fmaf(p, f, 0.69314718056f);
    p = fmaf(p, f, 1.0f);
    return p * __int_as_float((n + 127) << 23);
}

__device__ __forceinline__ void mma_tf32(float c[4], const uint32_t a[4],
                                         uint32_t b0, uint32_t b1) {
    asm volatile(
        "mma.sync.aligned.m16n8k8.row.col.f32.tf32.tf32.f32 "
        "{%0,%1,%2,%3}, {%4,%5,%6,%7}, {%8,%9}, {%0,%1,%2,%3};"
        : "+f"(c[0]), "+f"(c[1]), "+f"(c[2]), "+f"(c[3])
        : "r"(a[0]), "r"(a[1]), "r"(a[2]), "r"(a[3]), "r"(b0), "r"(b1));
}

// ---------------------------------------------------------------------------
// TF32 tensor-core NT GEMM (unchanged from round 2)
// ---------------------------------------------------------------------------
#define BM 128
#define BN 64
#define BK 32
#define SPAD 36

__global__ __launch_bounds__(256) void gemm_tf32_kernel(
    const float* __restrict__ A_in, const float* __restrict__ W,
    float* __restrict__ out_plain, int mode)
{
    __shared__ float As[BM][SPAD];
    __shared__ float Bs[BN][SPAD];

    const float* A = (mode == 3) ? g_ctx : A_in;

    const int tid  = threadIdx.x;
    const int lane = tid & 31;
    const int wid  = tid >> 5;
    const int gid  = lane >> 2;
    const int tig  = lane & 3;
    const int wm   = wid >> 1;
    const int wn   = wid & 1;
    const int bm   = blockIdx.y * BM;
    const int bn   = blockIdx.x * BN;

    const int lr = tid >> 3;
    const int lc = (tid & 7) * 4;

    float c[2][4][4];
    #pragma unroll
    for (int mt = 0; mt < 2; mt++)
        #pragma unroll
        for (int nt = 0; nt < 4; nt++)
            #pragma unroll
            for (int i = 0; i < 4; i++) c[mt][nt][i] = 0.f;

    for (int k0 = 0; k0 < C_DIM; k0 += BK) {
        #pragma unroll
        for (int i = 0; i < 4; i++) {
            float4 v = *(const float4*)(A + (size_t)(bm + lr + i * 32) * C_DIM + k0 + lc);
            As[lr + i * 32][lc + 0] = cvt_tf32(v.x);
            As[lr + i * 32][lc + 1] = cvt_tf32(v.y);
            As[lr + i * 32][lc + 2] = cvt_tf32(v.z);
            As[lr + i * 32][lc + 3] = cvt_tf32(v.w);
        }
        #pragma unroll
        for (int i = 0; i < 2; i++) {
            float4 v = *(const float4*)(W + (size_t)(bn + lr + i * 32) * C_DIM + k0 + lc);
            Bs[lr + i * 32][lc + 0] = cvt_tf32(v.x);
            Bs[lr + i * 32][lc + 1] = cvt_tf32(v.y);
            Bs[lr + i * 32][lc + 2] = cvt_tf32(v.z);
            Bs[lr + i * 32][lc + 3] = cvt_tf32(v.w);
        }
        __syncthreads();

        #pragma unroll
        for (int kk = 0; kk < 4; kk++) {
            const int k8 = kk * 8;
            uint32_t a[2][4], b[4][2];
            #pragma unroll
            for (int mt = 0; mt < 2; mt++) {
                int r = wm * 32 + mt * 16 + gid;
                a[mt][0] = __float_as_uint(As[r    ][k8 + tig]);
                a[mt][1] = __float_as_uint(As[r + 8][k8 + tig]);
                a[mt][2] = __float_as_uint(As[r    ][k8 + tig + 4]);
                a[mt][3] = __float_as_uint(As[r + 8][k8 + tig + 4]);
            }
            #pragma unroll
            for (int nt = 0; nt < 4; nt++) {
                int cn = wn * 32 + nt * 8 + gid;
                b[nt][0] = __float_as_uint(Bs[cn][k8 + tig]);
                b[nt][1] = __float_as_uint(Bs[cn][k8 + tig + 4]);
            }
            #pragma unroll
            for (int mt = 0; mt < 2; mt++)
                #pragma unroll
                for (int nt = 0; nt < 4; nt++)
                    mma_tf32(c[mt][nt], a[mt], b[nt][0], b[nt][1]);
        }
        __syncthreads();
    }

    if (mode == 3) {
        #pragma unroll
        for (int mt = 0; mt < 2; mt++)
            #pragma unroll
            for (int nt = 0; nt < 4; nt++) {
                int row0 = bm + wm * 32 + mt * 16 + gid;
                int col0 = bn + wn * 32 + nt * 8 + tig * 2;
                *(float2*)(out_plain + (size_t)row0 * C_DIM + col0) =
                    make_float2(c[mt][nt][0], c[mt][nt][1]);
                *(float2*)(out_plain + (size_t)(row0 + 8) * C_DIM + col0) =
                    make_float2(c[mt][nt][2], c[mt][nt][3]);
            }
    } else {
        float* dst = (mode == 0) ? g_q : (mode == 1) ? g_k : g_v;
        #pragma unroll
        for (int mt = 0; mt < 2; mt++)
            #pragma unroll
            for (int nt = 0; nt < 4; nt++) {
                int row0 = bm + wm * 32 + mt * 16 + gid;
                int col0 = bn + wn * 32 + nt * 8 + tig * 2;
                #pragma unroll
                for (int i = 0; i < 4; i++) {
                    int m = row0 + (i >> 1) * 8;
                    int n = col0 + (i & 1);
                    int t = m / B_SZ, bb = m % B_SZ;
                    int hh = n >> 6, d = n & 63;
                    dst[(((size_t)bb * H_NUM + hh) * T_SEQ + t) * D_HEAD + d] = c[mt][nt][i];
                }
            }
    }
}

// ---------------------------------------------------------------------------
// Tensor-core causal flash attention (tf32 mma, poly-exp softmax).
// 256 threads = 8 warps; each warp owns 16 q rows (q tile = 128).
// K/V tiles: 64 x 64 in smem (pads 68 / 72 -> conflict-free b-frag loads).
// grid = (T/128, H, B), heavy blocks first.
// ---------------------------------------------------------------------------
__global__ __launch_bounds__(256) void attn_tc_kernel()
{
    const int qb = (gridDim.x - 1) - blockIdx.x;
    const int h  = blockIdx.y;
    const int b  = blockIdx.z;
    const size_t base = (((size_t)b * H_NUM + h) * T_SEQ) * D_HEAD;
    const float* Qp = g_q + base;
    const float* Kp = g_k + base;
    const float* Vp = g_v + base;

    const int tid  = threadIdx.x;
    const int lane = tid & 31;
    const int wid  = tid >> 5;
    const int gid  = lane >> 2;   // 0..7
    const int tig  = lane & 3;    // 0..3

    __shared__ float Ks[64][68];  // 17.4 KB
    __shared__ float Vs[64][72];  // 18.4 KB

    const int t0 = qb * 128 + wid * 16 + gid;  // this thread's q rows
    const int t1 = t0 + 8;

    // Q a-frags (scale folded in), kept in registers for all K tiles
    uint32_t qa[8][4];
    #pragma unroll
    for (int kk = 0; kk < 8; kk++) {
        qa[kk][0] = __float_as_uint(cvt_tf32(Qp[(size_t)t0 * 64 + kk * 8 + tig] * 0.125f));
        qa[kk][1] = __float_as_uint(cvt_tf32(Qp[(size_t)t1 * 64 + kk * 8 + tig] * 0.125f));
        qa[kk][2] = __float_as_uint(cvt_tf32(Qp[(size_t)t0 * 64 + kk * 8 + tig + 4] * 0.125f));
        qa[kk][3] = __float_as_uint(cvt_tf32(Qp[(size_t)t1 * 64 + kk * 8 + tig + 4] * 0.125f));
    }

    float m0 = -1e30f, m1 = -1e30f, l0 = 0.f, l1 = 0.f;
    float o[8][4];
    #pragma unroll
    for (int nt = 0; nt < 8; nt++)
        #pragma unroll
        for (int i = 0; i < 4; i++) o[nt][i] = 0.f;

    const int nkb = qb * 2 + 2;    // 64-wide K tiles up to & including diagonal
    for (int kb = 0; kb < nkb; kb++) {
        // stage K,V tiles (tf32-converted)
        #pragma unroll
        for (int it = 0; it < 4; it++) {
            int idx = tid + it * 256;
            int r = idx >> 4;
            int c = (idx & 15) * 4;
            float4 kv = *(const float4*)(Kp + (size_t)(kb * 64 + r) * 64 + c);
            *(float4*)&Ks[r][c] = make_float4(cvt_tf32(kv.x), cvt_tf32(kv.y),
                                              cvt_tf32(kv.z), cvt_tf32(kv.w));
            float4 vv = *(const float4*)(Vp + (size_t)(kb * 64 + r) * 64 + c);
            *(float4*)&Vs[r][c] = make_float4(cvt_tf32(vv.x), cvt_tf32(vv.y),
                                              cvt_tf32(vv.z), cvt_tf32(vv.w));
        }
        __syncthreads();

        // S = Q @ K^T (pre-scaled)
        float s[8][4];
        #pragma unroll
        for (int nt = 0; nt < 8; nt++)
            #pragma unroll
            for (int i = 0; i < 4; i++) s[nt][i] = 0.f;

        #pragma unroll
        for (int kk = 0; kk < 8; kk++) {
            #pragma unroll
            for (int nt = 0; nt < 8; nt++) {
                uint32_t b0 = __float_as_uint(Ks[nt * 8 + gid][kk * 8 + tig]);
                uint32_t b1 = __float_as_uint(Ks[nt * 8 + gid][kk * 8 + tig + 4]);
                mma_tf32(s[nt], qa[kk], b0, b1);
            }
        }

        // causal mask (only the last two tiles straddle the diagonal)
        if (kb >= qb * 2) {
            #pragma unroll
            for (int nt = 0; nt < 8; nt++) {
                int cg = kb * 64 + nt * 8 + tig * 2;
                if (cg     > t0) s[nt][0] = -1e30f;
                if (cg + 1 > t0) s[nt][1] = -1e30f;
                if (cg     > t1) s[nt][2] = -1e30f;
                if (cg + 1 > t1) s[nt][3] = -1e30f;
            }
        }

        // online softmax (rows are warp+quad private)
        float mb0 = m0, mb1 = m1;
        #pragma unroll
        for (int nt = 0; nt < 8; nt++) {
            mb0 = fmaxf(mb0, fmaxf(s[nt][0], s[nt][1]));
            mb1 = fmaxf(mb1, fmaxf(s[nt][2], s[nt][3]));
        }
        mb0 = fmaxf(mb0, __shfl_xor_sync(0xffffffffu, mb0, 1));
        mb0 = fmaxf(mb0, __shfl_xor_sync(0xffffffffu, mb0, 2));
        mb1 = fmaxf(mb1, __shfl_xor_sync(0xffffffffu, mb1, 1));
        mb1 = fmaxf(mb1, __shfl_xor_sync(0xffffffffu, mb1, 2));

        float corr0 = fast_exp(m0 - mb0);
        float corr1 = fast_exp(m1 - mb1);
        m0 = mb0; m1 = mb1;
        l0 *= corr0; l1 *= corr1;
        #pragma unroll
        for (int nt = 0; nt < 8; nt++) {
            o[nt][0] *= corr0; o[nt][1] *= corr0;
            o[nt][2] *= corr1; o[nt][3] *= corr1;
        }

        #pragma unroll
        for (int nt = 0; nt < 8; nt++) {
            s[nt][0] = fast_exp(s[nt][0] - m0);
            s[nt][1] = fast_exp(s[nt][1] - m0);
            s[nt][2] = fast_exp(s[nt][2] - m1);
            s[nt][3] = fast_exp(s[nt][3] - m1);
            l0 += s[nt][0] + s[nt][1];
            l1 += s[nt][2] + s[nt][3];
        }

        // O += P @ V  (P c-frags -> a-frags via quad shuffles)
        #pragma unroll
        for (int kk = 0; kk < 8; kk++) {
            int src  = (lane & ~3) | (tig >> 1);
            int src2 = src + 2;
            float v00 = __shfl_sync(0xffffffffu, s[kk][0], src);
            float v01 = __shfl_sync(0xffffffffu, s[kk][1], src);
            float v10 = __shfl_sync(0xffffffffu, s[kk][2], src);
            float v11 = __shfl_sync(0xffffffffu, s[kk][3], src);
            float w00 = __shfl_sync(0xffffffffu, s[kk][0], src2);
            float w01 = __shfl_sync(0xffffffffu, s[kk][1], src2);
            float w10 = __shfl_sync(0xffffffffu, s[kk][2], src2);
            float w11 = __shfl_sync(0xffffffffu, s[kk][3], src2);
            bool odd = (tig & 1);
            uint32_t pa[4];
            pa[0] = __float_as_uint(cvt_tf32(odd ? v01 : v00));
            pa[1] = __float_as_uint(cvt_tf32(odd ? v11 : v10));
            pa[2] = __float_as_uint(cvt_tf32(odd ? w01 : w00));
            pa[3] = __float_as_uint(cvt_tf32(odd ? w11 : w10));
            #pragma unroll
            for (int nt = 0; nt < 8; nt++) {
                uint32_t b0 = __float_as_uint(Vs[kk * 8 + tig    ][nt * 8 + gid]);
                uint32_t b1 = __float_as_uint(Vs[kk * 8 + tig + 4][nt * 8 + gid]);
                mma_tf32(o[nt], pa, b0, b1);
            }
        }
        __syncthreads();
    }

    // normalize (l lives replicated per quad pair -> reduce across quad)
    l0 += __shfl_xor_sync(0xffffffffu, l0, 1);
    l0 += __shfl_xor_sync(0xffffffffu, l0, 2);
    l1 += __shfl_xor_sync(0xffffffffu, l1, 1);
    l1 += __shfl_xor_sync(0xffffffffu, l1, 2);
    float inv0 = 1.f / l0;
    float inv1 = 1.f / l1;

    #pragma unroll
    for (int nt = 0; nt < 8; nt++) {
        int col = h * 64 + nt * 8 + tig * 2;
        *(float2*)(g_ctx + ((size_t)t0 * B_SZ + b) * C_DIM + col) =
            make_float2(o[nt][0] * inv0, o[nt][1] * inv0);
        *(float2*)(g_ctx + ((size_t)t1 * B_SZ + b) * C_DIM + col) =
            make_float2(o[nt][2] * inv1, o[nt][3] * inv1);
    }
}

// ---------------------------------------------------------------------------
extern "C" void kernel_launch(void* const* d_in, const int* in_sizes, int n_in,
                              void* d_out, int out_size)
{
    const float* x  = (const float*)d_in[0];
    const float* Wq = (const float*)d_in[1];
    const float* Wk = (const float*)d_in[2];
    const float* Wv = (const float*)d_in[3];
    const float* Wo = (const float*)d_in[4];
    float* out = (float*)d_out;

    dim3 gg(C_DIM / BN, M_ROWS / BM);
    gemm_tf32_kernel<<<gg, 256>>>(x, Wq, nullptr, 0);
    gemm_tf32_kernel<<<gg, 256>>>(x, Wk, nullptr, 1);
    gemm_tf32_kernel<<<gg, 256>>>(x, Wv, nullptr, 2);

    dim3 ga(T_SEQ / 128, H_NUM, B_SZ);
    attn_tc_kernel<<<ga, 256>>>();

    gemm_tf32_kernel<<<gg, 256>>>(nullptr, Wo, out, 3);
}